// round 2
// baseline (speedup 1.0000x reference)
#include <cuda_runtime.h>

// Problem constants
#define BB 4
#define NTOK 4096           // H*W = 64*64
#define CC 64
#define TOKENS (BB*NTOK)    // 16384

// Scratch (device globals: allocation-free)
__device__ float g_xn[TOKENS*CC];
__device__ float g_q[TOKENS*CC];
__device__ float g_k[TOKENS*CC];
__device__ float g_v[TOKENS*CC];
__device__ float g_proj[TOKENS*CC];
__device__ float g_stats[64];   // 32 (b,g) pairs * {mean, rstd}

// ---------------------------------------------------------------------------
// Kernel 1: GroupNorm statistics. grid = 32 (b*8+g), block = 256.
// Each group = contiguous 8*64*64 = 32768 floats.
// ---------------------------------------------------------------------------
__global__ __launch_bounds__(256) void gn_stats_kernel(const float* __restrict__ x)
{
    int bg = blockIdx.x;
    const float* base = x + (size_t)bg * 32768;
    int tid = threadIdx.x;
    float s = 0.f, ss = 0.f;
    for (int i = tid * 4; i < 32768; i += 256 * 4) {
        float4 t = *(const float4*)(base + i);
        s  += t.x + t.y + t.z + t.w;
        ss += t.x*t.x + t.y*t.y + t.z*t.z + t.w*t.w;
    }
    __shared__ float rs[256], rq[256];
    rs[tid] = s; rq[tid] = ss;
    __syncthreads();
    for (int off = 128; off > 0; off >>= 1) {
        if (tid < off) { rs[tid] += rs[tid+off]; rq[tid] += rq[tid+off]; }
        __syncthreads();
    }
    if (tid == 0) {
        float mean = rs[0] * (1.f/32768.f);
        float var  = rq[0] * (1.f/32768.f) - mean*mean;
        g_stats[bg*2]   = mean;
        g_stats[bg*2+1] = rsqrtf(var + 1e-5f);
    }
}

// ---------------------------------------------------------------------------
// Kernel 2: GroupNorm apply + Q/K/V projection. grid = 256 tiles of 64 tokens
// (one tile = one (b,h) row, so gamma/beta/mean/rstd are scalars per tile).
// q is pre-scaled by C^-0.5 = 0.125 (including its bias).
// ---------------------------------------------------------------------------
__global__ __launch_bounds__(256) void qkv_kernel(
    const float* __restrict__ x, const float* __restrict__ gamma, const float* __restrict__ beta,
    const float* __restrict__ Wq, const float* __restrict__ bq,
    const float* __restrict__ Wk, const float* __restrict__ bk,
    const float* __restrict__ Wv, const float* __restrict__ bv)
{
    __shared__ __align__(16) float xnT[64*68];   // [c][w]
    __shared__ __align__(16) float Ws[64*68];    // [ic][oc]
    __shared__ float bias[3*64];
    int tid = threadIdx.x, tx = tid & 15, ty = tid >> 4;
    int bh = blockIdx.x;
    int b = bh >> 6, h = bh & 63, g = h >> 3;
    float mean = g_stats[(b*8+g)*2], rstd = g_stats[(b*8+g)*2+1];
    float ga = gamma[h] * rstd;
    float be = beta[h] - mean * ga;
    const float* xb = x + (size_t)bh * 4096;
    if (tid < 64) {
        bias[tid]       = bq[tid];
        bias[64 + tid]  = bk[tid];
        bias[128 + tid] = bv[tid];
    }
#pragma unroll
    for (int r = 0; r < 4; r++) {
        int idx = tid + 256*r;
        int w = idx >> 4, c4 = idx & 15;
        float4 t = *(const float4*)(xb + w*64 + c4*4);
        t.x = t.x*ga + be; t.y = t.y*ga + be; t.z = t.z*ga + be; t.w = t.w*ga + be;
        *(float4*)(g_xn + (size_t)bh*4096 + w*64 + c4*4) = t;
        xnT[(c4*4+0)*68 + w] = t.x; xnT[(c4*4+1)*68 + w] = t.y;
        xnT[(c4*4+2)*68 + w] = t.z; xnT[(c4*4+3)*68 + w] = t.w;
    }
    __syncthreads();

    for (int m = 0; m < 3; m++) {
        const float* W = (m == 0) ? Wq : (m == 1) ? Wk : Wv;
#pragma unroll
        for (int r = 0; r < 4; r++) {
            int idx = tid + 256*r;
            int row = idx >> 4, c4 = idx & 15;
            *(float4*)&Ws[row*68 + c4*4] = *(const float4*)(W + row*64 + c4*4);
        }
        __syncthreads();
        float acc[4][4];
#pragma unroll
        for (int i = 0; i < 4; i++)
#pragma unroll
            for (int j = 0; j < 4; j++) acc[i][j] = bias[m*64 + 4*tx + j];
#pragma unroll 8
        for (int d = 0; d < 64; d++) {
            float4 a  = *(float4*)&xnT[d*68 + 4*ty];
            float4 w4 = *(float4*)&Ws[d*68 + 4*tx];
            float av[4] = {a.x, a.y, a.z, a.w};
            float wv[4] = {w4.x, w4.y, w4.z, w4.w};
#pragma unroll
            for (int i = 0; i < 4; i++)
#pragma unroll
                for (int j = 0; j < 4; j++) acc[i][j] += av[i]*wv[j];
        }
        float sc = (m == 0) ? 0.125f : 1.0f;
        float* outp = (m == 0) ? g_q : (m == 1) ? g_k : g_v;
#pragma unroll
        for (int i = 0; i < 4; i++) {
            float4 r4;
            r4.x = acc[i][0]*sc; r4.y = acc[i][1]*sc;
            r4.z = acc[i][2]*sc; r4.w = acc[i][3]*sc;
            *(float4*)(outp + (size_t)bh*4096 + (4*ty+i)*64 + 4*tx) = r4;
        }
        __syncthreads();
    }
}

// ---------------------------------------------------------------------------
// Kernel 3: attention core. grid = (64 query tiles, 4 batches), block = 256.
// 64 queries x 4096 keys, d=64, fp32. One-pass unnormalized softmax
// (logits ~ N(0,1): exp never overflows; identical math to ref softmax).
// smem: qT/kT k-major (conflict-free LDS.128), v row-major, pT stride-65.
// ---------------------------------------------------------------------------
#define ATTN_SMEM ((3*64*68 + 64*65) * 4)

__global__ __launch_bounds__(256, 3) void attn_kernel()
{
    extern __shared__ __align__(16) float smem[];
    float* qT = smem;                 // [d][qi], stride 68
    float* kT = smem + 64*68;         // [d][ki], stride 68
    float* vs = smem + 2*64*68;       // [ki][c], stride 68
    float* pT = smem + 3*64*68;       // [ki][qi], stride 65

    int tid = threadIdx.x, tx = tid & 15, ty = tid >> 4;
    int qt = blockIdx.x, b = blockIdx.y;

    const float* qb = g_q + ((size_t)b*4096 + qt*64) * 64;
#pragma unroll
    for (int r = 0; r < 4; r++) {
        int idx = tid + 256*r;
        int tok = idx >> 4, d4 = idx & 15;
        float4 t = *(const float4*)(qb + tok*64 + d4*4);
        qT[(d4*4+0)*68 + tok] = t.x; qT[(d4*4+1)*68 + tok] = t.y;
        qT[(d4*4+2)*68 + tok] = t.z; qT[(d4*4+3)*68 + tok] = t.w;
    }
    float o[4][4] = {};
    float dsum[4] = {0.f, 0.f, 0.f, 0.f};
    const float* kbase = g_k + (size_t)b * 4096 * 64;
    const float* vbase = g_v + (size_t)b * 4096 * 64;
    __syncthreads();

    for (int kt = 0; kt < 64; kt++) {
        const float* kb = kbase + kt * 4096;
        const float* vb = vbase + kt * 4096;
#pragma unroll
        for (int r = 0; r < 4; r++) {
            int idx = tid + 256*r;
            int tok = idx >> 4, d4 = idx & 15;
            float4 t = *(const float4*)(kb + tok*64 + d4*4);
            kT[(d4*4+0)*68 + tok] = t.x; kT[(d4*4+1)*68 + tok] = t.y;
            kT[(d4*4+2)*68 + tok] = t.z; kT[(d4*4+3)*68 + tok] = t.w;
            float4 u = *(const float4*)(vb + tok*64 + d4*4);
            *(float4*)&vs[tok*68 + d4*4] = u;
        }
        __syncthreads();

        // S = Q K^T (scale pre-folded into q)
        float s[4][4] = {};
#pragma unroll 8
        for (int d = 0; d < 64; d++) {
            float4 a  = *(float4*)&qT[d*68 + 4*ty];
            float4 bb = *(float4*)&kT[d*68 + 4*tx];
            float av[4]  = {a.x, a.y, a.z, a.w};
            float bv4[4] = {bb.x, bb.y, bb.z, bb.w};
#pragma unroll
            for (int i = 0; i < 4; i++)
#pragma unroll
                for (int j = 0; j < 4; j++) s[i][j] += av[i]*bv4[j];
        }
        // P = exp(S); accumulate row sums; stage P transposed
#pragma unroll
        for (int i = 0; i < 4; i++)
#pragma unroll
            for (int j = 0; j < 4; j++) {
                float p = __expf(s[i][j]);
                dsum[i] += p;
                pT[(4*tx+j)*65 + 4*ty + i] = p;
            }
        __syncthreads();

        // O += P V
#pragma unroll 8
        for (int ki = 0; ki < 64; ki++) {
            float4 bv = *(float4*)&vs[ki*68 + 4*tx];
            float a0 = pT[ki*65 + 4*ty + 0];
            float a1 = pT[ki*65 + 4*ty + 1];
            float a2 = pT[ki*65 + 4*ty + 2];
            float a3 = pT[ki*65 + 4*ty + 3];
            o[0][0] += a0*bv.x; o[0][1] += a0*bv.y; o[0][2] += a0*bv.z; o[0][3] += a0*bv.w;
            o[1][0] += a1*bv.x; o[1][1] += a1*bv.y; o[1][2] += a1*bv.z; o[1][3] += a1*bv.w;
            o[2][0] += a2*bv.x; o[2][1] += a2*bv.y; o[2][2] += a2*bv.z; o[2][3] += a2*bv.w;
            o[3][0] += a3*bv.x; o[3][1] += a3*bv.y; o[3][2] += a3*bv.z; o[3][3] += a3*bv.w;
        }
        __syncthreads();
    }

    // Reduce denominators across the 16 tx lanes sharing each query row
#pragma unroll
    for (int i = 0; i < 4; i++) pT[(4*ty+i)*65 + tx] = dsum[i];
    __syncthreads();

    float* outb = g_proj + ((size_t)b*4096 + qt*64) * 64;
#pragma unroll
    for (int i = 0; i < 4; i++) {
        float dt = 0.f;
#pragma unroll
        for (int t = 0; t < 16; t++) dt += pT[(4*ty+i)*65 + t];
        float inv = 1.0f / dt;
        float4 r4;
        r4.x = o[i][0]*inv; r4.y = o[i][1]*inv; r4.z = o[i][2]*inv; r4.w = o[i][3]*inv;
        *(float4*)(outb + (4*ty+i)*64 + 4*tx) = r4;
    }
}

// ---------------------------------------------------------------------------
// Kernel 4: output projection + residual. grid = 256 tiles of 64 tokens.
// out = xn + proj @ Wo + bo
// ---------------------------------------------------------------------------
__global__ __launch_bounds__(256) void outproj_kernel(
    const float* __restrict__ Wo, const float* __restrict__ bo, float* __restrict__ out)
{
    __shared__ __align__(16) float pT[64*68];
    __shared__ __align__(16) float Ws[64*68];
    __shared__ float bias[64];
    int tid = threadIdx.x, tx = tid & 15, ty = tid >> 4;
    int bh = blockIdx.x;
    const float* pb = g_proj + (size_t)bh * 4096;
    if (tid < 64) bias[tid] = bo[tid];
#pragma unroll
    for (int r = 0; r < 4; r++) {
        int idx = tid + 256*r;
        int w = idx >> 4, c4 = idx & 15;
        float4 t = *(const float4*)(pb + w*64 + c4*4);
        pT[(c4*4+0)*68 + w] = t.x; pT[(c4*4+1)*68 + w] = t.y;
        pT[(c4*4+2)*68 + w] = t.z; pT[(c4*4+3)*68 + w] = t.w;
        *(float4*)&Ws[w*68 + c4*4] = *(const float4*)(Wo + w*64 + c4*4);
    }
    __syncthreads();
    float acc[4][4];
#pragma unroll
    for (int i = 0; i < 4; i++)
#pragma unroll
        for (int j = 0; j < 4; j++) acc[i][j] = bias[4*tx + j];
#pragma unroll 8
    for (int d = 0; d < 64; d++) {
        float4 a  = *(float4*)&pT[d*68 + 4*ty];
        float4 w4 = *(float4*)&Ws[d*68 + 4*tx];
        float av[4] = {a.x, a.y, a.z, a.w};
        float wv[4] = {w4.x, w4.y, w4.z, w4.w};
#pragma unroll
        for (int i = 0; i < 4; i++)
#pragma unroll
            for (int j = 0; j < 4; j++) acc[i][j] += av[i]*wv[j];
    }
#pragma unroll
    for (int i = 0; i < 4; i++) {
        float4 xv = *(const float4*)(g_xn + (size_t)bh*4096 + (4*ty+i)*64 + 4*tx);
        float4 r4;
        r4.x = acc[i][0] + xv.x; r4.y = acc[i][1] + xv.y;
        r4.z = acc[i][2] + xv.z; r4.w = acc[i][3] + xv.w;
        *(float4*)(out + (size_t)bh*4096 + (4*ty+i)*64 + 4*tx) = r4;
    }
}

// ---------------------------------------------------------------------------
extern "C" void kernel_launch(void* const* d_in, const int* in_sizes, int n_in,
                              void* d_out, int out_size)
{
    const float* x     = (const float*)d_in[0];
    const float* gamma = (const float*)d_in[1];
    const float* beta  = (const float*)d_in[2];
    const float* Wq    = (const float*)d_in[3];
    const float* bq    = (const float*)d_in[4];
    const float* Wk    = (const float*)d_in[5];
    const float* bk    = (const float*)d_in[6];
    const float* Wv    = (const float*)d_in[7];
    const float* bv    = (const float*)d_in[8];
    const float* Wo    = (const float*)d_in[9];
    const float* bo    = (const float*)d_in[10];
    float* out = (float*)d_out;

    cudaFuncSetAttribute(attn_kernel, cudaFuncAttributeMaxDynamicSharedMemorySize, ATTN_SMEM);

    gn_stats_kernel<<<32, 256>>>(x);
    qkv_kernel<<<256, 256>>>(x, gamma, beta, Wq, bq, Wk, bk, Wv, bv);
    attn_kernel<<<dim3(64, 4), 256, ATTN_SMEM>>>();
    outproj_kernel<<<256, 256>>>(Wo, bo, out);
}

// round 3
// speedup vs baseline: 4.0923x; 4.0923x over previous
#include <cuda_runtime.h>
#include <cuda_bf16.h>
#include <cstdint>

// Problem constants
#define BB 4
#define NTOK 4096           // H*W = 64*64
#define CC 64
#define TOKENS (BB*NTOK)    // 16384

// Scratch (device globals: allocation-free)
__device__ float g_xn[TOKENS*CC];
__device__ float g_proj[TOKENS*CC];
__device__ float g_stats[64];   // 32 (b,g) pairs * {mean, rstd}
__device__ __align__(16) __nv_bfloat16 g_qh[TOKENS*CC];
__device__ __align__(16) __nv_bfloat16 g_ql[TOKENS*CC];
__device__ __align__(16) __nv_bfloat16 g_kh[TOKENS*CC];
__device__ __align__(16) __nv_bfloat16 g_kl[TOKENS*CC];
__device__ __align__(16) __nv_bfloat16 g_vb[TOKENS*CC];

// ---------------------------------------------------------------------------
// Kernel 1: GroupNorm statistics. grid = 32 (b*8+g), block = 256.
// ---------------------------------------------------------------------------
__global__ __launch_bounds__(256) void gn_stats_kernel(const float* __restrict__ x)
{
    int bg = blockIdx.x;
    const float* base = x + (size_t)bg * 32768;
    int tid = threadIdx.x;
    float s = 0.f, ss = 0.f;
    for (int i = tid * 4; i < 32768; i += 256 * 4) {
        float4 t = *(const float4*)(base + i);
        s  += t.x + t.y + t.z + t.w;
        ss += t.x*t.x + t.y*t.y + t.z*t.z + t.w*t.w;
    }
    __shared__ float rs[256], rq[256];
    rs[tid] = s; rq[tid] = ss;
    __syncthreads();
    for (int off = 128; off > 0; off >>= 1) {
        if (tid < off) { rs[tid] += rs[tid+off]; rq[tid] += rq[tid+off]; }
        __syncthreads();
    }
    if (tid == 0) {
        float mean = rs[0] * (1.f/32768.f);
        float var  = rq[0] * (1.f/32768.f) - mean*mean;
        g_stats[bg*2]   = mean;
        g_stats[bg*2+1] = rsqrtf(var + 1e-5f);
    }
}

// ---------------------------------------------------------------------------
// Kernel 2: GroupNorm apply + Q/K/V projection; emit split-bf16 q/k, bf16 v.
// q is pre-scaled by C^-0.5 = 0.125 (exact power of two; split stays exact).
// ---------------------------------------------------------------------------
__global__ __launch_bounds__(256) void qkv_kernel(
    const float* __restrict__ x, const float* __restrict__ gamma, const float* __restrict__ beta,
    const float* __restrict__ Wq, const float* __restrict__ bq,
    const float* __restrict__ Wk, const float* __restrict__ bk,
    const float* __restrict__ Wv, const float* __restrict__ bv)
{
    __shared__ __align__(16) float xnT[64*68];   // [c][w]
    __shared__ __align__(16) float Ws[64*68];    // [ic][oc]
    __shared__ float bias[3*64];
    int tid = threadIdx.x, tx = tid & 15, ty = tid >> 4;
    int bh = blockIdx.x;
    int b = bh >> 6, h = bh & 63, g = h >> 3;
    float mean = g_stats[(b*8+g)*2], rstd = g_stats[(b*8+g)*2+1];
    float ga = gamma[h] * rstd;
    float be = beta[h] - mean * ga;
    const float* xb = x + (size_t)bh * 4096;
    if (tid < 64) {
        bias[tid]       = bq[tid];
        bias[64 + tid]  = bk[tid];
        bias[128 + tid] = bv[tid];
    }
#pragma unroll
    for (int r = 0; r < 4; r++) {
        int idx = tid + 256*r;
        int w = idx >> 4, c4 = idx & 15;
        float4 t = *(const float4*)(xb + w*64 + c4*4);
        t.x = t.x*ga + be; t.y = t.y*ga + be; t.z = t.z*ga + be; t.w = t.w*ga + be;
        *(float4*)(g_xn + (size_t)bh*4096 + w*64 + c4*4) = t;
        xnT[(c4*4+0)*68 + w] = t.x; xnT[(c4*4+1)*68 + w] = t.y;
        xnT[(c4*4+2)*68 + w] = t.z; xnT[(c4*4+3)*68 + w] = t.w;
    }
    __syncthreads();

    for (int m = 0; m < 3; m++) {
        const float* W = (m == 0) ? Wq : (m == 1) ? Wk : Wv;
#pragma unroll
        for (int r = 0; r < 4; r++) {
            int idx = tid + 256*r;
            int row = idx >> 4, c4 = idx & 15;
            *(float4*)&Ws[row*68 + c4*4] = *(const float4*)(W + row*64 + c4*4);
        }
        __syncthreads();
        float acc[4][4];
#pragma unroll
        for (int i = 0; i < 4; i++)
#pragma unroll
            for (int j = 0; j < 4; j++) acc[i][j] = bias[m*64 + 4*tx + j];
#pragma unroll 8
        for (int d = 0; d < 64; d++) {
            float4 a  = *(float4*)&xnT[d*68 + 4*ty];
            float4 w4 = *(float4*)&Ws[d*68 + 4*tx];
            float av[4] = {a.x, a.y, a.z, a.w};
            float wv[4] = {w4.x, w4.y, w4.z, w4.w};
#pragma unroll
            for (int i = 0; i < 4; i++)
#pragma unroll
                for (int j = 0; j < 4; j++) acc[i][j] += av[i]*wv[j];
        }
        float sc = (m == 0) ? 0.125f : 1.0f;
#pragma unroll
        for (int i = 0; i < 4; i++) {
            size_t idx = ((size_t)bh*64 + (4*ty+i))*64 + 4*tx;
            if (m < 2) {
                __nv_bfloat16* oh = (m == 0) ? g_qh : g_kh;
                __nv_bfloat16* ol = (m == 0) ? g_ql : g_kl;
#pragma unroll
                for (int j = 0; j < 4; j += 2) {
                    float v0 = acc[i][j]*sc, v1 = acc[i][j+1]*sc;
                    __nv_bfloat16 h0 = __float2bfloat16(v0), h1 = __float2bfloat16(v1);
                    __nv_bfloat16 l0 = __float2bfloat16(v0 - __bfloat162float(h0));
                    __nv_bfloat16 l1 = __float2bfloat16(v1 - __bfloat162float(h1));
                    __nv_bfloat162 ph; ph.x = h0; ph.y = h1;
                    __nv_bfloat162 pl; pl.x = l0; pl.y = l1;
                    *(__nv_bfloat162*)(oh + idx + j) = ph;
                    *(__nv_bfloat162*)(ol + idx + j) = pl;
                }
            } else {
#pragma unroll
                for (int j = 0; j < 4; j += 2) {
                    __nv_bfloat162 pv;
                    pv.x = __float2bfloat16(acc[i][j]);
                    pv.y = __float2bfloat16(acc[i][j+1]);
                    *(__nv_bfloat162*)(g_vb + idx + j) = pv;
                }
            }
        }
        __syncthreads();
    }
}

// ---------------------------------------------------------------------------
// Kernel 3: attention core on tensor cores (mma.sync m16n8k16 bf16, fp32 acc).
// CTA: 128 queries x 256 threads (8 warps x 16 rows). Key tiles of 64,
// double-buffered via cp.async. S = qh*kh + qh*kl + ql*kh (split-bf16).
// One-pass unnormalized softmax; P->A-frag reuse (FA2 layout identity).
// ---------------------------------------------------------------------------
#define KSTR 72
#define MATS (64*KSTR)      // 4608 bf16 per matrix
#define BUFS (3*MATS)       // kh, kl, v
#define ATTN_SMEM (2*BUFS*2) // bytes, two stages

#define MMA_BF16(D, A, B0, B1) asm volatile( \
    "mma.sync.aligned.m16n8k16.row.col.f32.bf16.bf16.f32 " \
    "{%0,%1,%2,%3}, {%4,%5,%6,%7}, {%8,%9}, {%0,%1,%2,%3};" \
    : "+f"(D[0]), "+f"(D[1]), "+f"(D[2]), "+f"(D[3]) \
    : "r"(A[0]), "r"(A[1]), "r"(A[2]), "r"(A[3]), "r"(B0), "r"(B1))

#define LDSM4(R, ADDR) asm volatile( \
    "ldmatrix.sync.aligned.m8n8.x4.shared.b16 {%0,%1,%2,%3}, [%4];" \
    : "=r"(R[0]), "=r"(R[1]), "=r"(R[2]), "=r"(R[3]) : "r"(ADDR))

#define LDSM4T(R, ADDR) asm volatile( \
    "ldmatrix.sync.aligned.m8n8.x4.trans.shared.b16 {%0,%1,%2,%3}, [%4];" \
    : "=r"(R[0]), "=r"(R[1]), "=r"(R[2]), "=r"(R[3]) : "r"(ADDR))

__device__ __forceinline__ uint32_t pack_bf16x2(float lo, float hi) {
    uint32_t r;
    asm("cvt.rn.bf16x2.f32 %0, %1, %2;" : "=r"(r) : "f"(hi), "f"(lo));
    return r;
}

__device__ __forceinline__ void prefetch_tile(
    uint32_t smem_base, int bufsel, int kt, int tid,
    const __nv_bfloat16* khb, const __nv_bfloat16* klb, const __nv_bfloat16* vbb)
{
    uint32_t dbase = smem_base + (bufsel ? (uint32_t)(BUFS*2) : 0u);
#pragma unroll
    for (int m = 0; m < 3; m++) {
        const __nv_bfloat16* gsrc =
            ((m == 0) ? khb : (m == 1) ? klb : vbb) + (size_t)kt*64*64;
#pragma unroll
        for (int r = 0; r < 2; r++) {
            int chunk = tid + 256*r;
            int key = chunk >> 3, c8 = chunk & 7;
            uint32_t dst = dbase + (uint32_t)(m*MATS + key*KSTR + c8*8)*2u;
            const void* src = gsrc + key*64 + c8*8;
            asm volatile("cp.async.cg.shared.global [%0], [%1], 16;" :: "r"(dst), "l"(src));
        }
    }
    asm volatile("cp.async.commit_group;");
}

__global__ __launch_bounds__(256) void attn_kernel()
{
    extern __shared__ __align__(16) __nv_bfloat16 sm[];
    int tid = threadIdx.x, w = tid >> 5, lane = tid & 31;
    int qt = blockIdx.x, b = blockIdx.y;
    uint32_t smem_base = (uint32_t)__cvta_generic_to_shared(sm);

    const size_t qofs = ((size_t)b*4096 + qt*128) * 64;
    uint32_t qfh[4][4], qfl[4][4];
    uint32_t rowa = smem_base + (uint32_t)((16*w + (lane & 15))*KSTR)*2u;

    // Stage q_hi, extract A-fragments
    {
        const __nv_bfloat16* src = g_qh + qofs;
#pragma unroll
        for (int r = 0; r < 4; r++) {
            int c = tid + 256*r;
            int row = c >> 3, c8 = c & 7;
            *(uint4*)(sm + row*KSTR + c8*8) = *(const uint4*)(src + row*64 + c8*8);
        }
        __syncthreads();
#pragma unroll
        for (int t = 0; t < 4; t++) {
            uint32_t addr = rowa + (uint32_t)(16*t + 8*(lane >> 4))*2u;
            LDSM4(qfh[t], addr);
        }
        __syncthreads();
    }
    // Stage q_lo, extract A-fragments
    {
        const __nv_bfloat16* src = g_ql + qofs;
#pragma unroll
        for (int r = 0; r < 4; r++) {
            int c = tid + 256*r;
            int row = c >> 3, c8 = c & 7;
            *(uint4*)(sm + row*KSTR + c8*8) = *(const uint4*)(src + row*64 + c8*8);
        }
        __syncthreads();
#pragma unroll
        for (int t = 0; t < 4; t++) {
            uint32_t addr = rowa + (uint32_t)(16*t + 8*(lane >> 4))*2u;
            LDSM4(qfl[t], addr);
        }
        __syncthreads();
    }

    const __nv_bfloat16* khb = g_kh + (size_t)b*4096*64;
    const __nv_bfloat16* klb = g_kl + (size_t)b*4096*64;
    const __nv_bfloat16* vbb = g_vb + (size_t)b*4096*64;

    float o[8][4];
#pragma unroll
    for (int i = 0; i < 8; i++)
#pragma unroll
        for (int j = 0; j < 4; j++) o[i][j] = 0.f;
    float rs0 = 0.f, rs1 = 0.f;

    prefetch_tile(smem_base, 0, 0, tid, khb, klb, vbb);

    for (int kt = 0; kt < 64; kt++) {
        asm volatile("cp.async.wait_group 0;" ::: "memory");
        __syncthreads();
        if (kt + 1 < 64)
            prefetch_tile(smem_base, (kt + 1) & 1, kt + 1, tid, khb, klb, vbb);

        uint32_t base = smem_base + ((kt & 1) ? (uint32_t)(BUFS*2) : 0u);

        // ---- S = Q K^T over 8 n-tiles of 8 keys
        float s[8][4];
#pragma unroll
        for (int j = 0; j < 8; j++) {
            s[j][0] = s[j][1] = s[j][2] = s[j][3] = 0.f;
            uint32_t kaddr = base + (uint32_t)((8*j + (lane & 7))*KSTR + 8*(lane >> 3))*2u;
            uint32_t kh0[4], kh1[4], kl0[4], kl1[4];
            LDSM4(kh0, kaddr);
            LDSM4(kh1, kaddr + 64u);
            LDSM4(kl0, kaddr + (uint32_t)(MATS*2));
            LDSM4(kl1, kaddr + (uint32_t)(MATS*2) + 64u);
            MMA_BF16(s[j], qfh[0], kh0[0], kh0[1]);
            MMA_BF16(s[j], qfh[1], kh0[2], kh0[3]);
            MMA_BF16(s[j], qfh[2], kh1[0], kh1[1]);
            MMA_BF16(s[j], qfh[3], kh1[2], kh1[3]);
            MMA_BF16(s[j], qfh[0], kl0[0], kl0[1]);
            MMA_BF16(s[j], qfh[1], kl0[2], kl0[3]);
            MMA_BF16(s[j], qfh[2], kl1[0], kl1[1]);
            MMA_BF16(s[j], qfh[3], kl1[2], kl1[3]);
            MMA_BF16(s[j], qfl[0], kh0[0], kh0[1]);
            MMA_BF16(s[j], qfl[1], kh0[2], kh0[3]);
            MMA_BF16(s[j], qfl[2], kh1[0], kh1[1]);
            MMA_BF16(s[j], qfl[3], kh1[2], kh1[3]);
        }

        // ---- P = exp(S) in regs; pack to bf16 A-fragments; accumulate sums
        uint32_t pa[4][4];
#pragma unroll
        for (int j = 0; j < 8; j += 2) {
            float e00 = __expf(s[j][0]),   e01 = __expf(s[j][1]);
            float e02 = __expf(s[j][2]),   e03 = __expf(s[j][3]);
            float e10 = __expf(s[j+1][0]), e11 = __expf(s[j+1][1]);
            float e12 = __expf(s[j+1][2]), e13 = __expf(s[j+1][3]);
            rs0 += e00 + e01 + e10 + e11;
            rs1 += e02 + e03 + e12 + e13;
            pa[j>>1][0] = pack_bf16x2(e00, e01);
            pa[j>>1][1] = pack_bf16x2(e02, e03);
            pa[j>>1][2] = pack_bf16x2(e10, e11);
            pa[j>>1][3] = pack_bf16x2(e12, e13);
        }

        // ---- O += P V over 8 channel-tiles
#pragma unroll
        for (int cj = 0; cj < 8; cj++) {
            uint32_t vaddr = base + (uint32_t)(2*MATS + lane*KSTR + 8*cj)*2u;
            uint32_t vf0[4], vf1[4];
            LDSM4T(vf0, vaddr);
            LDSM4T(vf1, vaddr + (uint32_t)(32*KSTR*2));
            MMA_BF16(o[cj], pa[0], vf0[0], vf0[1]);
            MMA_BF16(o[cj], pa[1], vf0[2], vf0[3]);
            MMA_BF16(o[cj], pa[2], vf1[0], vf1[1]);
            MMA_BF16(o[cj], pa[3], vf1[2], vf1[3]);
        }
    }

    // ---- finalize: reduce denominators over quad lanes, normalize, store
    rs0 += __shfl_xor_sync(0xffffffffu, rs0, 1);
    rs0 += __shfl_xor_sync(0xffffffffu, rs0, 2);
    rs1 += __shfl_xor_sync(0xffffffffu, rs1, 1);
    rs1 += __shfl_xor_sync(0xffffffffu, rs1, 2);
    float inv0 = 1.f/rs0, inv1 = 1.f/rs1;

    int g = lane >> 2, c2 = (lane & 3)*2;
    int row0 = qt*128 + 16*w + g;
    float* ob = g_proj + ((size_t)b*4096 + row0)*64;
#pragma unroll
    for (int cj = 0; cj < 8; cj++) {
        float2 r0; r0.x = o[cj][0]*inv0; r0.y = o[cj][1]*inv0;
        float2 r1; r1.x = o[cj][2]*inv1; r1.y = o[cj][3]*inv1;
        *(float2*)(ob + 8*cj + c2)          = r0;
        *(float2*)(ob + 8*64 + 8*cj + c2)   = r1;
    }
}

// ---------------------------------------------------------------------------
// Kernel 4: output projection + residual. out = xn + proj @ Wo + bo
// ---------------------------------------------------------------------------
__global__ __launch_bounds__(256) void outproj_kernel(
    const float* __restrict__ Wo, const float* __restrict__ bo, float* __restrict__ out)
{
    __shared__ __align__(16) float pT[64*68];
    __shared__ __align__(16) float Ws[64*68];
    __shared__ float bias[64];
    int tid = threadIdx.x, tx = tid & 15, ty = tid >> 4;
    int bh = blockIdx.x;
    const float* pb = g_proj + (size_t)bh * 4096;
    if (tid < 64) bias[tid] = bo[tid];
#pragma unroll
    for (int r = 0; r < 4; r++) {
        int idx = tid + 256*r;
        int w = idx >> 4, c4 = idx & 15;
        float4 t = *(const float4*)(pb + w*64 + c4*4);
        pT[(c4*4+0)*68 + w] = t.x; pT[(c4*4+1)*68 + w] = t.y;
        pT[(c4*4+2)*68 + w] = t.z; pT[(c4*4+3)*68 + w] = t.w;
        *(float4*)&Ws[w*68 + c4*4] = *(const float4*)(Wo + w*64 + c4*4);
    }
    __syncthreads();
    float acc[4][4];
#pragma unroll
    for (int i = 0; i < 4; i++)
#pragma unroll
        for (int j = 0; j < 4; j++) acc[i][j] = bias[4*tx + j];
#pragma unroll 8
    for (int d = 0; d < 64; d++) {
        float4 a  = *(float4*)&pT[d*68 + 4*ty];
        float4 w4 = *(float4*)&Ws[d*68 + 4*tx];
        float av[4] = {a.x, a.y, a.z, a.w};
        float wv[4] = {w4.x, w4.y, w4.z, w4.w};
#pragma unroll
        for (int i = 0; i < 4; i++)
#pragma unroll
            for (int j = 0; j < 4; j++) acc[i][j] += av[i]*wv[j];
    }
#pragma unroll
    for (int i = 0; i < 4; i++) {
        float4 xv = *(const float4*)(g_xn + (size_t)bh*4096 + (4*ty+i)*64 + 4*tx);
        float4 r4;
        r4.x = acc[i][0] + xv.x; r4.y = acc[i][1] + xv.y;
        r4.z = acc[i][2] + xv.z; r4.w = acc[i][3] + xv.w;
        *(float4*)(out + (size_t)bh*4096 + (4*ty+i)*64 + 4*tx) = r4;
    }
}

// ---------------------------------------------------------------------------
extern "C" void kernel_launch(void* const* d_in, const int* in_sizes, int n_in,
                              void* d_out, int out_size)
{
    const float* x     = (const float*)d_in[0];
    const float* gamma = (const float*)d_in[1];
    const float* beta  = (const float*)d_in[2];
    const float* Wq    = (const float*)d_in[3];
    const float* bq    = (const float*)d_in[4];
    const float* Wk    = (const float*)d_in[5];
    const float* bk    = (const float*)d_in[6];
    const float* Wv    = (const float*)d_in[7];
    const float* bv    = (const float*)d_in[8];
    const float* Wo    = (const float*)d_in[9];
    const float* bo    = (const float*)d_in[10];
    float* out = (float*)d_out;

    cudaFuncSetAttribute(attn_kernel, cudaFuncAttributeMaxDynamicSharedMemorySize, ATTN_SMEM);

    gn_stats_kernel<<<32, 256>>>(x);
    qkv_kernel<<<256, 256>>>(x, gamma, beta, Wq, bq, Wk, bk, Wv, bv);
    attn_kernel<<<dim3(32, 4), 256, ATTN_SMEM>>>();
    outproj_kernel<<<256, 256>>>(Wo, bo, out);
}

// round 8
// speedup vs baseline: 4.6000x; 1.1241x over previous
#include <cuda_runtime.h>
#include <cuda_bf16.h>
#include <cstdint>

// Problem constants
#define BB 4
#define NTOK 4096           // H*W = 64*64
#define CC 64
#define TOKENS (BB*NTOK)    // 16384

// Scratch (device globals: allocation-free)
__device__ float g_xn[TOKENS*CC];
__device__ float g_part[512];   // 256 partial (s, ss) pairs
__device__ __align__(16) __nv_bfloat16 g_qh[TOKENS*CC];
__device__ __align__(16) __nv_bfloat16 g_kh[TOKENS*CC];
__device__ __align__(16) __nv_bfloat16 g_kl[TOKENS*CC];
__device__ __align__(16) __nv_bfloat16 g_vb[TOKENS*CC];

// ---------------------------------------------------------------------------
// Kernel 1: GroupNorm partial sums. grid = 256; each block sums a 4096-float
// slice (one eighth of one (b,g) group). FIX: full 4096 coverage per block.
// ---------------------------------------------------------------------------
__global__ __launch_bounds__(256) void gn_stats_kernel(const float* __restrict__ x)
{
    int bid = blockIdx.x;                 // bg = bid>>3, part = bid&7
    const float* base = x + (size_t)bid * 4096;
    int tid = threadIdx.x;
    float s = 0.f, ss = 0.f;
#pragma unroll
    for (int i = 0; i < 4; i++) {
        float4 t = *(const float4*)(base + tid*4 + i*1024);
        s  += t.x + t.y + t.z + t.w;
        ss += t.x*t.x + t.y*t.y + t.z*t.z + t.w*t.w;
    }
    __shared__ float rs[256], rq[256];
    rs[tid] = s; rq[tid] = ss;
    __syncthreads();
    for (int off = 128; off > 0; off >>= 1) {
        if (tid < off) { rs[tid] += rs[tid+off]; rq[tid] += rq[tid+off]; }
        __syncthreads();
    }
    if (tid == 0) {
        g_part[bid*2]   = rs[0];
        g_part[bid*2+1] = rq[0];
    }
}

// ---------------------------------------------------------------------------
// Kernel 2: GroupNorm apply + Q/K/V projection; q -> bf16 (pre-scaled 0.125),
// k -> split bf16 (hi+lo), v -> bf16.
// ---------------------------------------------------------------------------
__global__ __launch_bounds__(256) void qkv_kernel(
    const float* __restrict__ x, const float* __restrict__ gamma, const float* __restrict__ beta,
    const float* __restrict__ Wq, const float* __restrict__ bq,
    const float* __restrict__ Wk, const float* __restrict__ bk,
    const float* __restrict__ Wv, const float* __restrict__ bv)
{
    __shared__ __align__(16) float xnT[64*68];   // [c][w]
    __shared__ __align__(16) float Ws[64*68];    // [ic][oc]
    __shared__ float bias[3*64];
    int tid = threadIdx.x, tx = tid & 15, ty = tid >> 4;
    int bh = blockIdx.x;
    int b = bh >> 6, h = bh & 63, g = h >> 3;
    int bg = b*8 + g;
    float s = 0.f, ss = 0.f;
#pragma unroll
    for (int i = 0; i < 8; i++) {
        s  += g_part[(bg*8+i)*2];
        ss += g_part[(bg*8+i)*2+1];
    }
    float mean = s * (1.f/32768.f);
    float var  = ss * (1.f/32768.f) - mean*mean;
    float rstd = rsqrtf(var + 1e-5f);
    float ga = gamma[h] * rstd;
    float be = beta[h] - mean * ga;
    const float* xb = x + (size_t)bh * 4096;
    if (tid < 64) {
        bias[tid]       = bq[tid];
        bias[64 + tid]  = bk[tid];
        bias[128 + tid] = bv[tid];
    }
#pragma unroll
    for (int r = 0; r < 4; r++) {
        int idx = tid + 256*r;
        int w = idx >> 4, c4 = idx & 15;
        float4 t = *(const float4*)(xb + w*64 + c4*4);
        t.x = t.x*ga + be; t.y = t.y*ga + be; t.z = t.z*ga + be; t.w = t.w*ga + be;
        *(float4*)(g_xn + (size_t)bh*4096 + w*64 + c4*4) = t;
        xnT[(c4*4+0)*68 + w] = t.x; xnT[(c4*4+1)*68 + w] = t.y;
        xnT[(c4*4+2)*68 + w] = t.z; xnT[(c4*4+3)*68 + w] = t.w;
    }
    __syncthreads();

    for (int m = 0; m < 3; m++) {
        const float* W = (m == 0) ? Wq : (m == 1) ? Wk : Wv;
#pragma unroll
        for (int r = 0; r < 4; r++) {
            int idx = tid + 256*r;
            int row = idx >> 4, c4 = idx & 15;
            *(float4*)&Ws[row*68 + c4*4] = *(const float4*)(W + row*64 + c4*4);
        }
        __syncthreads();
        float acc[4][4];
#pragma unroll
        for (int i = 0; i < 4; i++)
#pragma unroll
            for (int j = 0; j < 4; j++) acc[i][j] = bias[m*64 + 4*tx + j];
#pragma unroll 8
        for (int d = 0; d < 64; d++) {
            float4 a  = *(float4*)&xnT[d*68 + 4*ty];
            float4 w4 = *(float4*)&Ws[d*68 + 4*tx];
            float av[4] = {a.x, a.y, a.z, a.w};
            float wv[4] = {w4.x, w4.y, w4.z, w4.w};
#pragma unroll
            for (int i = 0; i < 4; i++)
#pragma unroll
                for (int j = 0; j < 4; j++) acc[i][j] += av[i]*wv[j];
        }
#pragma unroll
        for (int i = 0; i < 4; i++) {
            size_t idx = ((size_t)bh*64 + (4*ty+i))*64 + 4*tx;
            if (m == 0) {
#pragma unroll
                for (int j = 0; j < 4; j += 2) {
                    __nv_bfloat162 p;
                    p.x = __float2bfloat16(acc[i][j]   * 0.125f);
                    p.y = __float2bfloat16(acc[i][j+1] * 0.125f);
                    *(__nv_bfloat162*)(g_qh + idx + j) = p;
                }
            } else if (m == 1) {
#pragma unroll
                for (int j = 0; j < 4; j += 2) {
                    float v0 = acc[i][j], v1 = acc[i][j+1];
                    __nv_bfloat16 h0 = __float2bfloat16(v0), h1 = __float2bfloat16(v1);
                    __nv_bfloat16 l0 = __float2bfloat16(v0 - __bfloat162float(h0));
                    __nv_bfloat16 l1 = __float2bfloat16(v1 - __bfloat162float(h1));
                    __nv_bfloat162 ph; ph.x = h0; ph.y = h1;
                    __nv_bfloat162 pl; pl.x = l0; pl.y = l1;
                    *(__nv_bfloat162*)(g_kh + idx + j) = ph;
                    *(__nv_bfloat162*)(g_kl + idx + j) = pl;
                }
            } else {
#pragma unroll
                for (int j = 0; j < 4; j += 2) {
                    __nv_bfloat162 pv;
                    pv.x = __float2bfloat16(acc[i][j]);
                    pv.y = __float2bfloat16(acc[i][j+1]);
                    *(__nv_bfloat162*)(g_vb + idx + j) = pv;
                }
            }
        }
        __syncthreads();
    }
}

// ---------------------------------------------------------------------------
// Kernel 3: attention core + fused output projection + residual.
// CTA: 128 queries x 256 threads. Key tiles of 64, cp.async double-buffered.
// S = qh*kh + qh*kl. One-pass unnormalized softmax; P->A-frag reuse.
// Epilogue: out = xn + proj @ Wo + bo via split-bf16 MMA (3 terms).
// ---------------------------------------------------------------------------
#define KSTR 72
#define MATS (64*KSTR)      // 4608 bf16 per matrix
#define BUFS (3*MATS)       // kh, kl, v
#define ATTN_SMEM (2*BUFS*2) // bytes, two stages

#define MMA_BF16(D, A, B0, B1) asm volatile( \
    "mma.sync.aligned.m16n8k16.row.col.f32.bf16.bf16.f32 " \
    "{%0,%1,%2,%3}, {%4,%5,%6,%7}, {%8,%9}, {%0,%1,%2,%3};" \
    : "+f"(D[0]), "+f"(D[1]), "+f"(D[2]), "+f"(D[3]) \
    : "r"(A[0]), "r"(A[1]), "r"(A[2]), "r"(A[3]), "r"(B0), "r"(B1))

#define LDSM4(R, ADDR) asm volatile( \
    "ldmatrix.sync.aligned.m8n8.x4.shared.b16 {%0,%1,%2,%3}, [%4];" \
    : "=r"(R[0]), "=r"(R[1]), "=r"(R[2]), "=r"(R[3]) : "r"(ADDR))

#define LDSM4T(R, ADDR) asm volatile( \
    "ldmatrix.sync.aligned.m8n8.x4.trans.shared.b16 {%0,%1,%2,%3}, [%4];" \
    : "=r"(R[0]), "=r"(R[1]), "=r"(R[2]), "=r"(R[3]) : "r"(ADDR))

__device__ __forceinline__ uint32_t pack_bf16x2(float lo, float hi) {
    uint32_t r;
    asm("cvt.rn.bf16x2.f32 %0, %1, %2;" : "=r"(r) : "f"(hi), "f"(lo));
    return r;
}

__device__ __forceinline__ uint32_t pack2(__nv_bfloat16 a, __nv_bfloat16 b) {
    __nv_bfloat162 t; t.x = a; t.y = b;
    return *reinterpret_cast<uint32_t*>(&t);
}

// split a float pair into hi bf16x2 and lo (residual) bf16x2
__device__ __forceinline__ void split2(float a, float b, uint32_t& h, uint32_t& l) {
    __nv_bfloat16 ha = __float2bfloat16(a), hb = __float2bfloat16(b);
    h = pack2(ha, hb);
    l = pack2(__float2bfloat16(a - __bfloat162float(ha)),
              __float2bfloat16(b - __bfloat162float(hb)));
}

__device__ __forceinline__ void prefetch_tile(
    uint32_t smem_base, int bufsel, int kt, int tid,
    const __nv_bfloat16* khb, const __nv_bfloat16* klb, const __nv_bfloat16* vbb)
{
    uint32_t dbase = smem_base + (bufsel ? (uint32_t)(BUFS*2) : 0u);
#pragma unroll
    for (int m = 0; m < 3; m++) {
        const __nv_bfloat16* gsrc =
            ((m == 0) ? khb : (m == 1) ? klb : vbb) + (size_t)kt*64*64;
#pragma unroll
        for (int r = 0; r < 2; r++) {
            int chunk = tid + 256*r;
            int key = chunk >> 3, c8 = chunk & 7;
            uint32_t dst = dbase + (uint32_t)(m*MATS + key*KSTR + c8*8)*2u;
            const void* src = gsrc + key*64 + c8*8;
            asm volatile("cp.async.cg.shared.global [%0], [%1], 16;" :: "r"(dst), "l"(src));
        }
    }
    asm volatile("cp.async.commit_group;");
}

__global__ __launch_bounds__(256) void attn_kernel(
    const float* __restrict__ Wo, const float* __restrict__ bo, float* __restrict__ out)
{
    extern __shared__ __align__(16) __nv_bfloat16 sm[];
    int tid = threadIdx.x, w = tid >> 5, lane = tid & 31;
    int qt = blockIdx.x, b = blockIdx.y;
    uint32_t smem_base = (uint32_t)__cvta_generic_to_shared(sm);

    const size_t qofs = ((size_t)b*4096 + qt*128) * 64;
    uint32_t qfh[4][4];
    uint32_t rowa = smem_base + (uint32_t)((16*w + (lane & 15))*KSTR)*2u;

    // Stage q (bf16), extract A-fragments
    {
        const __nv_bfloat16* src = g_qh + qofs;
#pragma unroll
        for (int r = 0; r < 4; r++) {
            int c = tid + 256*r;
            int row = c >> 3, c8 = c & 7;
            *(uint4*)(sm + row*KSTR + c8*8) = *(const uint4*)(src + row*64 + c8*8);
        }
        __syncthreads();
#pragma unroll
        for (int t = 0; t < 4; t++) {
            uint32_t addr = rowa + (uint32_t)(16*t + 8*(lane >> 4))*2u;
            LDSM4(qfh[t], addr);
        }
        __syncthreads();
    }

    const __nv_bfloat16* khb = g_kh + (size_t)b*4096*64;
    const __nv_bfloat16* klb = g_kl + (size_t)b*4096*64;
    const __nv_bfloat16* vbb = g_vb + (size_t)b*4096*64;

    float o[8][4];
#pragma unroll
    for (int i = 0; i < 8; i++)
#pragma unroll
        for (int j = 0; j < 4; j++) o[i][j] = 0.f;
    float rs0 = 0.f, rs1 = 0.f;

    prefetch_tile(smem_base, 0, 0, tid, khb, klb, vbb);

    for (int kt = 0; kt < 64; kt++) {
        asm volatile("cp.async.wait_group 0;" ::: "memory");
        __syncthreads();
        if (kt + 1 < 64)
            prefetch_tile(smem_base, (kt + 1) & 1, kt + 1, tid, khb, klb, vbb);

        uint32_t base = smem_base + ((kt & 1) ? (uint32_t)(BUFS*2) : 0u);

        // ---- S = Q K^T over 8 n-tiles of 8 keys (k split hi/lo)
        float s[8][4];
#pragma unroll
        for (int j = 0; j < 8; j++) {
            s[j][0] = s[j][1] = s[j][2] = s[j][3] = 0.f;
            uint32_t kaddr = base + (uint32_t)((8*j + (lane & 7))*KSTR + 8*(lane >> 3))*2u;
            uint32_t kh0[4], kh1[4], kl0[4], kl1[4];
            LDSM4(kh0, kaddr);
            LDSM4(kh1, kaddr + 64u);
            LDSM4(kl0, kaddr + (uint32_t)(MATS*2));
            LDSM4(kl1, kaddr + (uint32_t)(MATS*2) + 64u);
            MMA_BF16(s[j], qfh[0], kh0[0], kh0[1]);
            MMA_BF16(s[j], qfh[1], kh0[2], kh0[3]);
            MMA_BF16(s[j], qfh[2], kh1[0], kh1[1]);
            MMA_BF16(s[j], qfh[3], kh1[2], kh1[3]);
            MMA_BF16(s[j], qfh[0], kl0[0], kl0[1]);
            MMA_BF16(s[j], qfh[1], kl0[2], kl0[3]);
            MMA_BF16(s[j], qfh[2], kl1[0], kl1[1]);
            MMA_BF16(s[j], qfh[3], kl1[2], kl1[3]);
        }

        // ---- P = exp(S) in regs; pack to bf16 A-fragments; accumulate sums
        uint32_t pa[4][4];
#pragma unroll
        for (int j = 0; j < 8; j += 2) {
            float e00 = __expf(s[j][0]),   e01 = __expf(s[j][1]);
            float e02 = __expf(s[j][2]),   e03 = __expf(s[j][3]);
            float e10 = __expf(s[j+1][0]), e11 = __expf(s[j+1][1]);
            float e12 = __expf(s[j+1][2]), e13 = __expf(s[j+1][3]);
            rs0 += e00 + e01 + e10 + e11;
            rs1 += e02 + e03 + e12 + e13;
            pa[j>>1][0] = pack_bf16x2(e00, e01);
            pa[j>>1][1] = pack_bf16x2(e02, e03);
            pa[j>>1][2] = pack_bf16x2(e10, e11);
            pa[j>>1][3] = pack_bf16x2(e12, e13);
        }

        // ---- O += P V over 8 channel-tiles
#pragma unroll
        for (int cj = 0; cj < 8; cj++) {
            uint32_t vaddr = base + (uint32_t)(2*MATS + lane*KSTR + 8*cj)*2u;
            uint32_t vf0[4], vf1[4];
            LDSM4T(vf0, vaddr);
            LDSM4T(vf1, vaddr + (uint32_t)(32*KSTR*2));
            MMA_BF16(o[cj], pa[0], vf0[0], vf0[1]);
            MMA_BF16(o[cj], pa[1], vf0[2], vf0[3]);
            MMA_BF16(o[cj], pa[2], vf1[0], vf1[1]);
            MMA_BF16(o[cj], pa[3], vf1[2], vf1[3]);
        }
    }

    // ---- denominators: reduce over quad lanes
    rs0 += __shfl_xor_sync(0xffffffffu, rs0, 1);
    rs0 += __shfl_xor_sync(0xffffffffu, rs0, 2);
    rs1 += __shfl_xor_sync(0xffffffffu, rs1, 1);
    rs1 += __shfl_xor_sync(0xffffffffu, rs1, 2);
    float inv0 = 1.f/rs0, inv1 = 1.f/rs1;

    // ---- normalize proj and split into hi/lo bf16 A-fragments
    uint32_t ph[4][4], pl[4][4];
#pragma unroll
    for (int t = 0; t < 4; t++) {
        float v00 = o[2*t][0]*inv0,   v01 = o[2*t][1]*inv0;
        float v02 = o[2*t][2]*inv1,   v03 = o[2*t][3]*inv1;
        float v10 = o[2*t+1][0]*inv0, v11 = o[2*t+1][1]*inv0;
        float v12 = o[2*t+1][2]*inv1, v13 = o[2*t+1][3]*inv1;
        split2(v00, v01, ph[t][0], pl[t][0]);
        split2(v02, v03, ph[t][1], pl[t][1]);
        split2(v10, v11, ph[t][2], pl[t][2]);
        split2(v12, v13, ph[t][3], pl[t][3]);
    }

    // ---- stage Wo as split bf16 into stage-0 smem: hi at 0, lo at MATS
    {
        int ic = tid >> 2, oc0 = (tid & 3) * 16;
        const float* wrow = Wo + ic*64 + oc0;
        __nv_bfloat16* dsth = sm + ic*KSTR + oc0;
        __nv_bfloat16* dstl = sm + MATS + ic*KSTR + oc0;
#pragma unroll
        for (int u = 0; u < 4; u++) {
            float4 t = *(const float4*)(wrow + 4*u);
            __nv_bfloat16 h0 = __float2bfloat16(t.x), h1 = __float2bfloat16(t.y);
            __nv_bfloat16 h2 = __float2bfloat16(t.z), h3 = __float2bfloat16(t.w);
            *(uint32_t*)(dsth + 4*u)     = pack2(h0, h1);
            *(uint32_t*)(dsth + 4*u + 2) = pack2(h2, h3);
            *(uint32_t*)(dstl + 4*u)     = pack2(__float2bfloat16(t.x - __bfloat162float(h0)),
                                                 __float2bfloat16(t.y - __bfloat162float(h1)));
            *(uint32_t*)(dstl + 4*u + 2) = pack2(__float2bfloat16(t.z - __bfloat162float(h2)),
                                                 __float2bfloat16(t.w - __bfloat162float(h3)));
        }
    }
    __syncthreads();

    // ---- out = xn + proj @ Wo + bo (3-term split MMA)
    int gq = lane >> 2, c2 = (lane & 3)*2;
    int row0 = qt*128 + 16*w + gq;
    const float* xb0 = g_xn + ((size_t)b*4096 + row0)*64;
    float* outb = out + ((size_t)b*4096 + row0)*64;

#pragma unroll
    for (int cj = 0; cj < 8; cj++) {
        float acc[4] = {0.f, 0.f, 0.f, 0.f};
        uint32_t waddr = smem_base + (uint32_t)(lane*KSTR + 8*cj)*2u;
        uint32_t wh0[4], wh1[4], wl0[4], wl1[4];
        LDSM4T(wh0, waddr);
        LDSM4T(wh1, waddr + (uint32_t)(32*KSTR*2));
        LDSM4T(wl0, waddr + (uint32_t)(MATS*2));
        LDSM4T(wl1, waddr + (uint32_t)(MATS*2) + (uint32_t)(32*KSTR*2));
        MMA_BF16(acc, ph[0], wh0[0], wh0[1]);
        MMA_BF16(acc, ph[1], wh0[2], wh0[3]);
        MMA_BF16(acc, ph[2], wh1[0], wh1[1]);
        MMA_BF16(acc, ph[3], wh1[2], wh1[3]);
        MMA_BF16(acc, ph[0], wl0[0], wl0[1]);
        MMA_BF16(acc, ph[1], wl0[2], wl0[3]);
        MMA_BF16(acc, ph[2], wl1[0], wl1[1]);
        MMA_BF16(acc, ph[3], wl1[2], wl1[3]);
        MMA_BF16(acc, pl[0], wh0[0], wh0[1]);
        MMA_BF16(acc, pl[1], wh0[2], wh0[3]);
        MMA_BF16(acc, pl[2], wh1[0], wh1[1]);
        MMA_BF16(acc, pl[3], wh1[2], wh1[3]);

        float2 bo2 = *(const float2*)(bo + 8*cj + c2);
        float2 x0  = *(const float2*)(xb0 + 8*cj + c2);
        float2 x1  = *(const float2*)(xb0 + 8*64 + 8*cj + c2);
        float2 r0; r0.x = acc[0] + bo2.x + x0.x; r0.y = acc[1] + bo2.y + x0.y;
        float2 r1; r1.x = acc[2] + bo2.x + x1.x; r1.y = acc[3] + bo2.y + x1.y;
        *(float2*)(outb + 8*cj + c2)        = r0;
        *(float2*)(outb + 8*64 + 8*cj + c2) = r1;
    }
}

// ---------------------------------------------------------------------------
extern "C" void kernel_launch(void* const* d_in, const int* in_sizes, int n_in,
                              void* d_out, int out_size)
{
    const float* x     = (const float*)d_in[0];
    const float* gamma = (const float*)d_in[1];
    const float* beta  = (const float*)d_in[2];
    const float* Wq    = (const float*)d_in[3];
    const float* bq    = (const float*)d_in[4];
    const float* Wk    = (const float*)d_in[5];
    const float* bk    = (const float*)d_in[6];
    const float* Wv    = (const float*)d_in[7];
    const float* bv    = (const float*)d_in[8];
    const float* Wo    = (const float*)d_in[9];
    const float* bo    = (const float*)d_in[10];
    float* out = (float*)d_out;

    cudaFuncSetAttribute(attn_kernel, cudaFuncAttributeMaxDynamicSharedMemorySize, ATTN_SMEM);

    gn_stats_kernel<<<256, 256>>>(x);
    qkv_kernel<<<256, 256>>>(x, gamma, beta, Wq, bq, Wk, bk, Wv, bv);
    attn_kernel<<<dim3(32, 4), 256, ATTN_SMEM>>>(Wo, bo, out);
}

// round 9
// speedup vs baseline: 5.5725x; 1.2114x over previous
#include <cuda_runtime.h>
#include <cuda_fp16.h>
#include <cstdint>

// Problem constants
#define BB 4
#define NTOK 4096           // H*W = 64*64
#define CC 64
#define TOKENS (BB*NTOK)    // 16384

// Scratch (device globals: allocation-free)
__device__ float g_xn[TOKENS*CC];
__device__ float g_part[512];   // 256 partial (s, ss) pairs
__device__ __align__(16) __half g_qh[TOKENS*CC];
__device__ __align__(16) __half g_kh[TOKENS*CC];
__device__ __align__(16) __half g_vb[TOKENS*CC];

// ---------------------------------------------------------------------------
// Kernel 1: GroupNorm partial sums. grid = 256; each block sums a 4096-float
// slice (one eighth of one (b,g) group).
// ---------------------------------------------------------------------------
__global__ __launch_bounds__(256) void gn_stats_kernel(const float* __restrict__ x)
{
    int bid = blockIdx.x;                 // bg = bid>>3, part = bid&7
    const float* base = x + (size_t)bid * 4096;
    int tid = threadIdx.x;
    float s = 0.f, ss = 0.f;
#pragma unroll
    for (int i = 0; i < 4; i++) {
        float4 t = *(const float4*)(base + tid*4 + i*1024);
        s  += t.x + t.y + t.z + t.w;
        ss += t.x*t.x + t.y*t.y + t.z*t.z + t.w*t.w;
    }
    __shared__ float rs[256], rq[256];
    rs[tid] = s; rq[tid] = ss;
    __syncthreads();
    for (int off = 128; off > 0; off >>= 1) {
        if (tid < off) { rs[tid] += rs[tid+off]; rq[tid] += rq[tid+off]; }
        __syncthreads();
    }
    if (tid == 0) {
        g_part[bid*2]   = rs[0];
        g_part[bid*2+1] = rq[0];
    }
}

// ---------------------------------------------------------------------------
// Kernel 2: GroupNorm apply + Q/K/V projection -> fp16 (q pre-scaled 0.125).
// ---------------------------------------------------------------------------
__global__ __launch_bounds__(256) void qkv_kernel(
    const float* __restrict__ x, const float* __restrict__ gamma, const float* __restrict__ beta,
    const float* __restrict__ Wq, const float* __restrict__ bq,
    const float* __restrict__ Wk, const float* __restrict__ bk,
    const float* __restrict__ Wv, const float* __restrict__ bv)
{
    __shared__ __align__(16) float xnT[64*68];   // [c][w]
    __shared__ __align__(16) float Ws[64*68];    // [ic][oc]
    __shared__ float bias[3*64];
    int tid = threadIdx.x, tx = tid & 15, ty = tid >> 4;
    int bh = blockIdx.x;
    int b = bh >> 6, h = bh & 63, g = h >> 3;
    int bg = b*8 + g;
    float s = 0.f, ss = 0.f;
#pragma unroll
    for (int i = 0; i < 8; i++) {
        s  += g_part[(bg*8+i)*2];
        ss += g_part[(bg*8+i)*2+1];
    }
    float mean = s * (1.f/32768.f);
    float var  = ss * (1.f/32768.f) - mean*mean;
    float rstd = rsqrtf(var + 1e-5f);
    float ga = gamma[h] * rstd;
    float be = beta[h] - mean * ga;
    const float* xb = x + (size_t)bh * 4096;
    if (tid < 64) {
        bias[tid]       = bq[tid];
        bias[64 + tid]  = bk[tid];
        bias[128 + tid] = bv[tid];
    }
#pragma unroll
    for (int r = 0; r < 4; r++) {
        int idx = tid + 256*r;
        int w = idx >> 4, c4 = idx & 15;
        float4 t = *(const float4*)(xb + w*64 + c4*4);
        t.x = t.x*ga + be; t.y = t.y*ga + be; t.z = t.z*ga + be; t.w = t.w*ga + be;
        *(float4*)(g_xn + (size_t)bh*4096 + w*64 + c4*4) = t;
        xnT[(c4*4+0)*68 + w] = t.x; xnT[(c4*4+1)*68 + w] = t.y;
        xnT[(c4*4+2)*68 + w] = t.z; xnT[(c4*4+3)*68 + w] = t.w;
    }
    __syncthreads();

    for (int m = 0; m < 3; m++) {
        const float* W = (m == 0) ? Wq : (m == 1) ? Wk : Wv;
#pragma unroll
        for (int r = 0; r < 4; r++) {
            int idx = tid + 256*r;
            int row = idx >> 4, c4 = idx & 15;
            *(float4*)&Ws[row*68 + c4*4] = *(const float4*)(W + row*64 + c4*4);
        }
        __syncthreads();
        float acc[4][4];
#pragma unroll
        for (int i = 0; i < 4; i++)
#pragma unroll
            for (int j = 0; j < 4; j++) acc[i][j] = bias[m*64 + 4*tx + j];
#pragma unroll 8
        for (int d = 0; d < 64; d++) {
            float4 a  = *(float4*)&xnT[d*68 + 4*ty];
            float4 w4 = *(float4*)&Ws[d*68 + 4*tx];
            float av[4] = {a.x, a.y, a.z, a.w};
            float wv[4] = {w4.x, w4.y, w4.z, w4.w};
#pragma unroll
            for (int i = 0; i < 4; i++)
#pragma unroll
                for (int j = 0; j < 4; j++) acc[i][j] += av[i]*wv[j];
        }
        float sc = (m == 0) ? 0.125f : 1.0f;
        __half* outp = (m == 0) ? g_qh : (m == 1) ? g_kh : g_vb;
#pragma unroll
        for (int i = 0; i < 4; i++) {
            size_t idx = ((size_t)bh*64 + (4*ty+i))*64 + 4*tx;
#pragma unroll
            for (int j = 0; j < 4; j += 2) {
                __half2 p;
                p.x = __float2half_rn(acc[i][j]   * sc);
                p.y = __float2half_rn(acc[i][j+1] * sc);
                *(__half2*)(outp + idx + j) = p;
            }
        }
        __syncthreads();
    }
}

// ---------------------------------------------------------------------------
// Kernel 3: attention core + fused output projection + residual. All fp16
// operands, fp32 accumulate. CTA: 128 queries x 256 threads. Key tiles of 64,
// cp.async double-buffered (k, v). One-pass unnormalized softmax; exp of
// tile j-2 interleaved into the S-MMA loop to hide MUFU under tensor issue.
// Epilogue: out = xn + proj @ Wo + bo via split-fp16 MMA (3 terms).
// ---------------------------------------------------------------------------
#define KSTR 72
#define MATS (64*KSTR)      // 4608 halves per matrix
#define BUFS (2*MATS)       // k, v
#define ATTN_SMEM (2*BUFS*2) // bytes, two stages (36 KB)

#define MMA_F16(D, A, B0, B1) asm volatile( \
    "mma.sync.aligned.m16n8k16.row.col.f32.f16.f16.f32 " \
    "{%0,%1,%2,%3}, {%4,%5,%6,%7}, {%8,%9}, {%0,%1,%2,%3};" \
    : "+f"(D[0]), "+f"(D[1]), "+f"(D[2]), "+f"(D[3]) \
    : "r"(A[0]), "r"(A[1]), "r"(A[2]), "r"(A[3]), "r"(B0), "r"(B1))

#define LDSM4(R, ADDR) asm volatile( \
    "ldmatrix.sync.aligned.m8n8.x4.shared.b16 {%0,%1,%2,%3}, [%4];" \
    : "=r"(R[0]), "=r"(R[1]), "=r"(R[2]), "=r"(R[3]) : "r"(ADDR))

#define LDSM4T(R, ADDR) asm volatile( \
    "ldmatrix.sync.aligned.m8n8.x4.trans.shared.b16 {%0,%1,%2,%3}, [%4];" \
    : "=r"(R[0]), "=r"(R[1]), "=r"(R[2]), "=r"(R[3]) : "r"(ADDR))

__device__ __forceinline__ uint32_t pack_f16x2(float lo, float hi) {
    uint32_t r;
    asm("cvt.rn.f16x2.f32 %0, %1, %2;" : "=r"(r) : "f"(hi), "f"(lo));
    return r;
}

__device__ __forceinline__ uint32_t pack2h(__half a, __half b) {
    __half2 t; t.x = a; t.y = b;
    return *reinterpret_cast<uint32_t*>(&t);
}

// split a float pair into hi fp16x2 and lo (residual) fp16x2
__device__ __forceinline__ void split2h(float a, float b, uint32_t& h, uint32_t& l) {
    __half ha = __float2half_rn(a), hb = __float2half_rn(b);
    h = pack2h(ha, hb);
    l = pack2h(__float2half_rn(a - __half2float(ha)),
               __float2half_rn(b - __half2float(hb)));
}

__device__ __forceinline__ void prefetch_tile(
    uint32_t smem_base, int bufsel, int kt, int tid,
    const __half* khb, const __half* vbb)
{
    uint32_t dbase = smem_base + (bufsel ? (uint32_t)(BUFS*2) : 0u);
#pragma unroll
    for (int m = 0; m < 2; m++) {
        const __half* gsrc = ((m == 0) ? khb : vbb) + (size_t)kt*64*64;
#pragma unroll
        for (int r = 0; r < 2; r++) {
            int chunk = tid + 256*r;
            int key = chunk >> 3, c8 = chunk & 7;
            uint32_t dst = dbase + (uint32_t)(m*MATS + key*KSTR + c8*8)*2u;
            const void* src = gsrc + key*64 + c8*8;
            asm volatile("cp.async.cg.shared.global [%0], [%1], 16;" :: "r"(dst), "l"(src));
        }
    }
    asm volatile("cp.async.commit_group;");
}

__global__ __launch_bounds__(256) void attn_kernel(
    const float* __restrict__ Wo, const float* __restrict__ bo, float* __restrict__ out)
{
    extern __shared__ __align__(16) __half sm[];
    int tid = threadIdx.x, w = tid >> 5, lane = tid & 31;
    int qt = blockIdx.x, b = blockIdx.y;
    uint32_t smem_base = (uint32_t)__cvta_generic_to_shared(sm);

    const size_t qofs = ((size_t)b*4096 + qt*128) * 64;
    uint32_t qf[4][4];
    uint32_t rowa = smem_base + (uint32_t)((16*w + (lane & 15))*KSTR)*2u;

    // Stage q (fp16), extract A-fragments
    {
        const __half* src = g_qh + qofs;
#pragma unroll
        for (int r = 0; r < 4; r++) {
            int c = tid + 256*r;
            int row = c >> 3, c8 = c & 7;
            *(uint4*)(sm + row*KSTR + c8*8) = *(const uint4*)(src + row*64 + c8*8);
        }
        __syncthreads();
#pragma unroll
        for (int t = 0; t < 4; t++) {
            uint32_t addr = rowa + (uint32_t)(16*t + 8*(lane >> 4))*2u;
            LDSM4(qf[t], addr);
        }
        __syncthreads();
    }

    const __half* khb = g_kh + (size_t)b*4096*64;
    const __half* vbb = g_vb + (size_t)b*4096*64;

    float o[8][4];
#pragma unroll
    for (int i = 0; i < 8; i++)
#pragma unroll
        for (int j = 0; j < 4; j++) o[i][j] = 0.f;
    float rs0 = 0.f, rs1 = 0.f;

    prefetch_tile(smem_base, 0, 0, tid, khb, vbb);

    for (int kt = 0; kt < 64; kt++) {
        asm volatile("cp.async.wait_group 0;" ::: "memory");
        __syncthreads();
        if (kt + 1 < 64)
            prefetch_tile(smem_base, (kt + 1) & 1, kt + 1, tid, khb, vbb);

        uint32_t base = smem_base + ((kt & 1) ? (uint32_t)(BUFS*2) : 0u);

        // ---- S = Q K^T over 8 n-tiles of 8 keys; exp(j-2) interleaved
        float s[8][4];
        uint32_t pa[4][4];
#pragma unroll
        for (int j = 0; j < 8; j++) {
            s[j][0] = s[j][1] = s[j][2] = s[j][3] = 0.f;
            uint32_t kaddr = base + (uint32_t)((8*j + (lane & 7))*KSTR + 8*(lane >> 3))*2u;
            uint32_t k0[4], k1[4];
            LDSM4(k0, kaddr);
            LDSM4(k1, kaddr + 64u);
            MMA_F16(s[j], qf[0], k0[0], k0[1]);
            MMA_F16(s[j], qf[1], k0[2], k0[3]);
            MMA_F16(s[j], qf[2], k1[0], k1[1]);
            MMA_F16(s[j], qf[3], k1[2], k1[3]);
            if (j >= 2) {
                int e = j - 2;
                float e0 = __expf(s[e][0]), e1 = __expf(s[e][1]);
                float e2 = __expf(s[e][2]), e3 = __expf(s[e][3]);
                rs0 += e0 + e1;  rs1 += e2 + e3;
                pa[e>>1][(e&1)*2+0] = pack_f16x2(e0, e1);
                pa[e>>1][(e&1)*2+1] = pack_f16x2(e2, e3);
            }
        }
#pragma unroll
        for (int e = 6; e < 8; e++) {
            float e0 = __expf(s[e][0]), e1 = __expf(s[e][1]);
            float e2 = __expf(s[e][2]), e3 = __expf(s[e][3]);
            rs0 += e0 + e1;  rs1 += e2 + e3;
            pa[e>>1][(e&1)*2+0] = pack_f16x2(e0, e1);
            pa[e>>1][(e&1)*2+1] = pack_f16x2(e2, e3);
        }

        // ---- O += P V over 8 channel-tiles
#pragma unroll
        for (int cj = 0; cj < 8; cj++) {
            uint32_t vaddr = base + (uint32_t)(MATS + lane*KSTR + 8*cj)*2u;
            uint32_t vf0[4], vf1[4];
            LDSM4T(vf0, vaddr);
            LDSM4T(vf1, vaddr + (uint32_t)(32*KSTR*2));
            MMA_F16(o[cj], pa[0], vf0[0], vf0[1]);
            MMA_F16(o[cj], pa[1], vf0[2], vf0[3]);
            MMA_F16(o[cj], pa[2], vf1[0], vf1[1]);
            MMA_F16(o[cj], pa[3], vf1[2], vf1[3]);
        }
    }

    // ---- denominators: reduce over quad lanes
    rs0 += __shfl_xor_sync(0xffffffffu, rs0, 1);
    rs0 += __shfl_xor_sync(0xffffffffu, rs0, 2);
    rs1 += __shfl_xor_sync(0xffffffffu, rs1, 1);
    rs1 += __shfl_xor_sync(0xffffffffu, rs1, 2);
    float inv0 = 1.f/rs0, inv1 = 1.f/rs1;

    // ---- normalize proj and split into hi/lo fp16 A-fragments
    uint32_t ph[4][4], pl[4][4];
#pragma unroll
    for (int t = 0; t < 4; t++) {
        float v00 = o[2*t][0]*inv0,   v01 = o[2*t][1]*inv0;
        float v02 = o[2*t][2]*inv1,   v03 = o[2*t][3]*inv1;
        float v10 = o[2*t+1][0]*inv0, v11 = o[2*t+1][1]*inv0;
        float v12 = o[2*t+1][2]*inv1, v13 = o[2*t+1][3]*inv1;
        split2h(v00, v01, ph[t][0], pl[t][0]);
        split2h(v02, v03, ph[t][1], pl[t][1]);
        split2h(v10, v11, ph[t][2], pl[t][2]);
        split2h(v12, v13, ph[t][3], pl[t][3]);
    }

    __syncthreads();
    // ---- stage Wo as split fp16 into stage-0 smem: hi at 0, lo at MATS
    {
        int ic = tid >> 2, oc0 = (tid & 3) * 16;
        const float* wrow = Wo + ic*64 + oc0;
        __half* dsth = sm + ic*KSTR + oc0;
        __half* dstl = sm + MATS + ic*KSTR + oc0;
#pragma unroll
        for (int u = 0; u < 4; u++) {
            float4 t = *(const float4*)(wrow + 4*u);
            __half h0 = __float2half_rn(t.x), h1 = __float2half_rn(t.y);
            __half h2 = __float2half_rn(t.z), h3 = __float2half_rn(t.w);
            *(uint32_t*)(dsth + 4*u)     = pack2h(h0, h1);
            *(uint32_t*)(dsth + 4*u + 2) = pack2h(h2, h3);
            *(uint32_t*)(dstl + 4*u)     = pack2h(__float2half_rn(t.x - __half2float(h0)),
                                                  __float2half_rn(t.y - __half2float(h1)));
            *(uint32_t*)(dstl + 4*u + 2) = pack2h(__float2half_rn(t.z - __half2float(h2)),
                                                  __float2half_rn(t.w - __half2float(h3)));
        }
    }
    __syncthreads();

    // ---- out = xn + proj @ Wo + bo (3-term split MMA)
    int gq = lane >> 2, c2 = (lane & 3)*2;
    int row0 = qt*128 + 16*w + gq;
    const float* xb0 = g_xn + ((size_t)b*4096 + row0)*64;
    float* outb = out + ((size_t)b*4096 + row0)*64;

#pragma unroll
    for (int cj = 0; cj < 8; cj++) {
        float acc[4] = {0.f, 0.f, 0.f, 0.f};
        uint32_t waddr = smem_base + (uint32_t)(lane*KSTR + 8*cj)*2u;
        uint32_t wh0[4], wh1[4], wl0[4], wl1[4];
        LDSM4T(wh0, waddr);
        LDSM4T(wh1, waddr + (uint32_t)(32*KSTR*2));
        LDSM4T(wl0, waddr + (uint32_t)(MATS*2));
        LDSM4T(wl1, waddr + (uint32_t)(MATS*2) + (uint32_t)(32*KSTR*2));
        MMA_F16(acc, ph[0], wh0[0], wh0[1]);
        MMA_F16(acc, ph[1], wh0[2], wh0[3]);
        MMA_F16(acc, ph[2], wh1[0], wh1[1]);
        MMA_F16(acc, ph[3], wh1[2], wh1[3]);
        MMA_F16(acc, ph[0], wl0[0], wl0[1]);
        MMA_F16(acc, ph[1], wl0[2], wl0[3]);
        MMA_F16(acc, ph[2], wl1[0], wl1[1]);
        MMA_F16(acc, ph[3], wl1[2], wl1[3]);
        MMA_F16(acc, pl[0], wh0[0], wh0[1]);
        MMA_F16(acc, pl[1], wh0[2], wh0[3]);
        MMA_F16(acc, pl[2], wh1[0], wh1[1]);
        MMA_F16(acc, pl[3], wh1[2], wh1[3]);

        float2 bo2 = *(const float2*)(bo + 8*cj + c2);
        float2 x0  = *(const float2*)(xb0 + 8*cj + c2);
        float2 x1  = *(const float2*)(xb0 + 8*64 + 8*cj + c2);
        float2 r0; r0.x = acc[0] + bo2.x + x0.x; r0.y = acc[1] + bo2.y + x0.y;
        float2 r1; r1.x = acc[2] + bo2.x + x1.x; r1.y = acc[3] + bo2.y + x1.y;
        *(float2*)(outb + 8*cj + c2)        = r0;
        *(float2*)(outb + 8*64 + 8*cj + c2) = r1;
    }
}

// ---------------------------------------------------------------------------
extern "C" void kernel_launch(void* const* d_in, const int* in_sizes, int n_in,
                              void* d_out, int out_size)
{
    const float* x     = (const float*)d_in[0];
    const float* gamma = (const float*)d_in[1];
    const float* beta  = (const float*)d_in[2];
    const float* Wq    = (const float*)d_in[3];
    const float* bq    = (const float*)d_in[4];
    const float* Wk    = (const float*)d_in[5];
    const float* bk    = (const float*)d_in[6];
    const float* Wv    = (const float*)d_in[7];
    const float* bv    = (const float*)d_in[8];
    const float* Wo    = (const float*)d_in[9];
    const float* bo    = (const float*)d_in[10];
    float* out = (float*)d_out;

    cudaFuncSetAttribute(attn_kernel, cudaFuncAttributeMaxDynamicSharedMemorySize, ATTN_SMEM);

    gn_stats_kernel<<<256, 256>>>(x);
    qkv_kernel<<<256, 256>>>(x, gamma, beta, Wq, bq, Wk, bk, Wv, bv);
    attn_kernel<<<dim3(32, 4), 256, ATTN_SMEM>>>(Wo, bo, out);
}

// round 10
// speedup vs baseline: 6.6115x; 1.1865x over previous
#include <cuda_runtime.h>
#include <cuda_fp16.h>
#include <cstdint>

// Problem constants
#define BB 4
#define NTOK 4096           // H*W = 64*64
#define CC 64
#define TOKENS (BB*NTOK)    // 16384

// Scratch (device globals: allocation-free)
__device__ float g_xn[TOKENS*CC];
__device__ float g_part[512];   // 256 partial (s, ss) pairs
__device__ __align__(16) __half g_qh[TOKENS*CC];
__device__ __align__(16) __half g_kh[TOKENS*CC];
__device__ __align__(16) __half g_vb[TOKENS*CC];

// ---------------------------------------------------------------------------
// Kernel 1: GroupNorm partial sums. grid = 256; each block sums a 4096-float
// slice (one eighth of one (b,g) group).
// ---------------------------------------------------------------------------
__global__ __launch_bounds__(256) void gn_stats_kernel(const float* __restrict__ x)
{
    int bid = blockIdx.x;                 // bg = bid>>3, part = bid&7
    const float* base = x + (size_t)bid * 4096;
    int tid = threadIdx.x;
    float s = 0.f, ss = 0.f;
#pragma unroll
    for (int i = 0; i < 4; i++) {
        float4 t = *(const float4*)(base + tid*4 + i*1024);
        s  += t.x + t.y + t.z + t.w;
        ss += t.x*t.x + t.y*t.y + t.z*t.z + t.w*t.w;
    }
    __shared__ float rs[256], rq[256];
    rs[tid] = s; rq[tid] = ss;
    __syncthreads();
    for (int off = 128; off > 0; off >>= 1) {
        if (tid < off) { rs[tid] += rs[tid+off]; rq[tid] += rq[tid+off]; }
        __syncthreads();
    }
    if (tid == 0) {
        g_part[bid*2]   = rs[0];
        g_part[bid*2+1] = rq[0];
    }
}

// ---------------------------------------------------------------------------
// Kernel 2: GroupNorm apply + Q/K/V projection -> fp16.
// q pre-scaled by 0.125 * log2(e) so attention logits come out in log2 units.
// ---------------------------------------------------------------------------
__global__ __launch_bounds__(256) void qkv_kernel(
    const float* __restrict__ x, const float* __restrict__ gamma, const float* __restrict__ beta,
    const float* __restrict__ Wq, const float* __restrict__ bq,
    const float* __restrict__ Wk, const float* __restrict__ bk,
    const float* __restrict__ Wv, const float* __restrict__ bv)
{
    __shared__ __align__(16) float xnT[64*68];   // [c][w]
    __shared__ __align__(16) float Ws[64*68];    // [ic][oc]
    __shared__ float bias[3*64];
    int tid = threadIdx.x, tx = tid & 15, ty = tid >> 4;
    int bh = blockIdx.x;
    int b = bh >> 6, h = bh & 63, g = h >> 3;
    int bg = b*8 + g;
    float s = 0.f, ss = 0.f;
#pragma unroll
    for (int i = 0; i < 8; i++) {
        s  += g_part[(bg*8+i)*2];
        ss += g_part[(bg*8+i)*2+1];
    }
    float mean = s * (1.f/32768.f);
    float var  = ss * (1.f/32768.f) - mean*mean;
    float rstd = rsqrtf(var + 1e-5f);
    float ga = gamma[h] * rstd;
    float be = beta[h] - mean * ga;
    const float* xb = x + (size_t)bh * 4096;
    if (tid < 64) {
        bias[tid]       = bq[tid];
        bias[64 + tid]  = bk[tid];
        bias[128 + tid] = bv[tid];
    }
#pragma unroll
    for (int r = 0; r < 4; r++) {
        int idx = tid + 256*r;
        int w = idx >> 4, c4 = idx & 15;
        float4 t = *(const float4*)(xb + w*64 + c4*4);
        t.x = t.x*ga + be; t.y = t.y*ga + be; t.z = t.z*ga + be; t.w = t.w*ga + be;
        *(float4*)(g_xn + (size_t)bh*4096 + w*64 + c4*4) = t;
        xnT[(c4*4+0)*68 + w] = t.x; xnT[(c4*4+1)*68 + w] = t.y;
        xnT[(c4*4+2)*68 + w] = t.z; xnT[(c4*4+3)*68 + w] = t.w;
    }
    __syncthreads();

    for (int m = 0; m < 3; m++) {
        const float* W = (m == 0) ? Wq : (m == 1) ? Wk : Wv;
#pragma unroll
        for (int r = 0; r < 4; r++) {
            int idx = tid + 256*r;
            int row = idx >> 4, c4 = idx & 15;
            *(float4*)&Ws[row*68 + c4*4] = *(const float4*)(W + row*64 + c4*4);
        }
        __syncthreads();
        float acc[4][4];
#pragma unroll
        for (int i = 0; i < 4; i++)
#pragma unroll
            for (int j = 0; j < 4; j++) acc[i][j] = bias[m*64 + 4*tx + j];
#pragma unroll 8
        for (int d = 0; d < 64; d++) {
            float4 a  = *(float4*)&xnT[d*68 + 4*ty];
            float4 w4 = *(float4*)&Ws[d*68 + 4*tx];
            float av[4] = {a.x, a.y, a.z, a.w};
            float wv[4] = {w4.x, w4.y, w4.z, w4.w};
#pragma unroll
            for (int i = 0; i < 4; i++)
#pragma unroll
                for (int j = 0; j < 4; j++) acc[i][j] += av[i]*wv[j];
        }
        // q gets 0.125 * log2(e) so exp() can be done as exp2 in f16x2
        float sc = (m == 0) ? (0.125f * 1.44269504088896f) : 1.0f;
        __half* outp = (m == 0) ? g_qh : (m == 1) ? g_kh : g_vb;
#pragma unroll
        for (int i = 0; i < 4; i++) {
            size_t idx = ((size_t)bh*64 + (4*ty+i))*64 + 4*tx;
#pragma unroll
            for (int j = 0; j < 4; j += 2) {
                __half2 p;
                p.x = __float2half_rn(acc[i][j]   * sc);
                p.y = __float2half_rn(acc[i][j+1] * sc);
                *(__half2*)(outp + idx + j) = p;
            }
        }
        __syncthreads();
    }
}

// ---------------------------------------------------------------------------
// Kernel 3: attention core + fused output projection + residual. All fp16
// operands, fp32 accumulate. CTA: 128 queries x 256 threads. Key tiles of 64,
// cp.async double-buffered (k, v). Softmax: logits in log2 units ->
// P = ex2.approx.f16x2 directly into A-fragments; row sums via all-ones MMA
// (fp32-exact sum of the fp16 P, consistent with the PV numerator).
// Epilogue: out = xn + proj @ Wo + bo via split-fp16 MMA (3 terms).
// ---------------------------------------------------------------------------
#define KSTR 72
#define MATS (64*KSTR)      // 4608 halves per matrix
#define BUFS (2*MATS)       // k, v
#define ATTN_SMEM (2*BUFS*2) // bytes, two stages (36 KB)
#define ONES16 0x3C003C00u  // fp16x2 {1.0, 1.0}

#define MMA_F16(D, A, B0, B1) asm volatile( \
    "mma.sync.aligned.m16n8k16.row.col.f32.f16.f16.f32 " \
    "{%0,%1,%2,%3}, {%4,%5,%6,%7}, {%8,%9}, {%0,%1,%2,%3};" \
    : "+f"(D[0]), "+f"(D[1]), "+f"(D[2]), "+f"(D[3]) \
    : "r"(A[0]), "r"(A[1]), "r"(A[2]), "r"(A[3]), "r"(B0), "r"(B1))

#define LDSM4(R, ADDR) asm volatile( \
    "ldmatrix.sync.aligned.m8n8.x4.shared.b16 {%0,%1,%2,%3}, [%4];" \
    : "=r"(R[0]), "=r"(R[1]), "=r"(R[2]), "=r"(R[3]) : "r"(ADDR))

#define LDSM4T(R, ADDR) asm volatile( \
    "ldmatrix.sync.aligned.m8n8.x4.trans.shared.b16 {%0,%1,%2,%3}, [%4];" \
    : "=r"(R[0]), "=r"(R[1]), "=r"(R[2]), "=r"(R[3]) : "r"(ADDR))

__device__ __forceinline__ uint32_t pack_f16x2(float lo, float hi) {
    uint32_t r;
    asm("cvt.rn.f16x2.f32 %0, %1, %2;" : "=r"(r) : "f"(hi), "f"(lo));
    return r;
}

// P = 2^s for a pair of log2-domain logits, packed fp16x2
__device__ __forceinline__ uint32_t exp2_f16x2(float lo, float hi) {
    uint32_t p = pack_f16x2(lo, hi);
    uint32_t r;
    asm("ex2.approx.f16x2 %0, %1;" : "=r"(r) : "r"(p));
    return r;
}

__device__ __forceinline__ uint32_t pack2h(__half a, __half b) {
    __half2 t; t.x = a; t.y = b;
    return *reinterpret_cast<uint32_t*>(&t);
}

// split a float pair into hi fp16x2 and lo (residual) fp16x2
__device__ __forceinline__ void split2h(float a, float b, uint32_t& h, uint32_t& l) {
    __half ha = __float2half_rn(a), hb = __float2half_rn(b);
    h = pack2h(ha, hb);
    l = pack2h(__float2half_rn(a - __half2float(ha)),
               __float2half_rn(b - __half2float(hb)));
}

__device__ __forceinline__ void prefetch_tile(
    uint32_t smem_base, int bufsel, int kt, int tid,
    const __half* khb, const __half* vbb)
{
    uint32_t dbase = smem_base + (bufsel ? (uint32_t)(BUFS*2) : 0u);
#pragma unroll
    for (int m = 0; m < 2; m++) {
        const __half* gsrc = ((m == 0) ? khb : vbb) + (size_t)kt*64*64;
#pragma unroll
        for (int r = 0; r < 2; r++) {
            int chunk = tid + 256*r;
            int key = chunk >> 3, c8 = chunk & 7;
            uint32_t dst = dbase + (uint32_t)(m*MATS + key*KSTR + c8*8)*2u;
            const void* src = gsrc + key*64 + c8*8;
            asm volatile("cp.async.cg.shared.global [%0], [%1], 16;" :: "r"(dst), "l"(src));
        }
    }
    asm volatile("cp.async.commit_group;");
}

__global__ __launch_bounds__(256) void attn_kernel(
    const float* __restrict__ Wo, const float* __restrict__ bo, float* __restrict__ out)
{
    extern __shared__ __align__(16) __half sm[];
    int tid = threadIdx.x, w = tid >> 5, lane = tid & 31;
    int qt = blockIdx.x, b = blockIdx.y;
    uint32_t smem_base = (uint32_t)__cvta_generic_to_shared(sm);

    const size_t qofs = ((size_t)b*4096 + qt*128) * 64;
    uint32_t qf[4][4];
    uint32_t rowa = smem_base + (uint32_t)((16*w + (lane & 15))*KSTR)*2u;

    // Stage q (fp16), extract A-fragments
    {
        const __half* src = g_qh + qofs;
#pragma unroll
        for (int r = 0; r < 4; r++) {
            int c = tid + 256*r;
            int row = c >> 3, c8 = c & 7;
            *(uint4*)(sm + row*KSTR + c8*8) = *(const uint4*)(src + row*64 + c8*8);
        }
        __syncthreads();
#pragma unroll
        for (int t = 0; t < 4; t++) {
            uint32_t addr = rowa + (uint32_t)(16*t + 8*(lane >> 4))*2u;
            LDSM4(qf[t], addr);
        }
        __syncthreads();
    }

    const __half* khb = g_kh + (size_t)b*4096*64;
    const __half* vbb = g_vb + (size_t)b*4096*64;

    float o[8][4];
#pragma unroll
    for (int i = 0; i < 8; i++)
#pragma unroll
        for (int j = 0; j < 4; j++) o[i][j] = 0.f;
    float rsum[4] = {0.f, 0.f, 0.f, 0.f};   // all-ones MMA accumulator (row sums)

    prefetch_tile(smem_base, 0, 0, tid, khb, vbb);

    for (int kt = 0; kt < 64; kt++) {
        asm volatile("cp.async.wait_group 0;" ::: "memory");
        __syncthreads();
        if (kt + 1 < 64)
            prefetch_tile(smem_base, (kt + 1) & 1, kt + 1, tid, khb, vbb);

        uint32_t base = smem_base + ((kt & 1) ? (uint32_t)(BUFS*2) : 0u);

        // ---- S = Q K^T over 8 n-tiles of 8 keys (log2 domain)
        float s[8][4];
        uint32_t pa[4][4];
#pragma unroll
        for (int j = 0; j < 8; j++) {
            s[j][0] = s[j][1] = s[j][2] = s[j][3] = 0.f;
            uint32_t kaddr = base + (uint32_t)((8*j + (lane & 7))*KSTR + 8*(lane >> 3))*2u;
            uint32_t k0[4], k1[4];
            LDSM4(k0, kaddr);
            LDSM4(k1, kaddr + 64u);
            MMA_F16(s[j], qf[0], k0[0], k0[1]);
            MMA_F16(s[j], qf[1], k0[2], k0[3]);
            MMA_F16(s[j], qf[2], k1[0], k1[1]);
            MMA_F16(s[j], qf[3], k1[2], k1[3]);
            // interleave P for tile j-2 (cvt + f16x2 exp2, no fp32 MUFU)
            if (j >= 2) {
                int e = j - 2;
                pa[e>>1][(e&1)*2+0] = exp2_f16x2(s[e][0], s[e][1]);
                pa[e>>1][(e&1)*2+1] = exp2_f16x2(s[e][2], s[e][3]);
            }
        }
#pragma unroll
        for (int e = 6; e < 8; e++) {
            pa[e>>1][(e&1)*2+0] = exp2_f16x2(s[e][0], s[e][1]);
            pa[e>>1][(e&1)*2+1] = exp2_f16x2(s[e][2], s[e][3]);
        }

        // ---- row sums: P @ ones (fp32-exact sum of fp16 P)
        MMA_F16(rsum, pa[0], ONES16, ONES16);
        MMA_F16(rsum, pa[1], ONES16, ONES16);
        MMA_F16(rsum, pa[2], ONES16, ONES16);
        MMA_F16(rsum, pa[3], ONES16, ONES16);

        // ---- O += P V over 8 channel-tiles
#pragma unroll
        for (int cj = 0; cj < 8; cj++) {
            uint32_t vaddr = base + (uint32_t)(MATS + lane*KSTR + 8*cj)*2u;
            uint32_t vf0[4], vf1[4];
            LDSM4T(vf0, vaddr);
            LDSM4T(vf1, vaddr + (uint32_t)(32*KSTR*2));
            MMA_F16(o[cj], pa[0], vf0[0], vf0[1]);
            MMA_F16(o[cj], pa[1], vf0[2], vf0[3]);
            MMA_F16(o[cj], pa[2], vf1[0], vf1[1]);
            MMA_F16(o[cj], pa[3], vf1[2], vf1[3]);
        }
    }

    // ---- denominators come straight out of the ones-MMA accumulator
    float inv0 = 1.f / rsum[0];
    float inv1 = 1.f / rsum[2];

    // ---- normalize proj and split into hi/lo fp16 A-fragments
    uint32_t ph[4][4], pl[4][4];
#pragma unroll
    for (int t = 0; t < 4; t++) {
        float v00 = o[2*t][0]*inv0,   v01 = o[2*t][1]*inv0;
        float v02 = o[2*t][2]*inv1,   v03 = o[2*t][3]*inv1;
        float v10 = o[2*t+1][0]*inv0, v11 = o[2*t+1][1]*inv0;
        float v12 = o[2*t+1][2]*inv1, v13 = o[2*t+1][3]*inv1;
        split2h(v00, v01, ph[t][0], pl[t][0]);
        split2h(v02, v03, ph[t][1], pl[t][1]);
        split2h(v10, v11, ph[t][2], pl[t][2]);
        split2h(v12, v13, ph[t][3], pl[t][3]);
    }

    __syncthreads();
    // ---- stage Wo as split fp16 into stage-0 smem: hi at 0, lo at MATS
    {
        int ic = tid >> 2, oc0 = (tid & 3) * 16;
        const float* wrow = Wo + ic*64 + oc0;
        __half* dsth = sm + ic*KSTR + oc0;
        __half* dstl = sm + MATS + ic*KSTR + oc0;
#pragma unroll
        for (int u = 0; u < 4; u++) {
            float4 t = *(const float4*)(wrow + 4*u);
            __half h0 = __float2half_rn(t.x), h1 = __float2half_rn(t.y);
            __half h2 = __float2half_rn(t.z), h3 = __float2half_rn(t.w);
            *(uint32_t*)(dsth + 4*u)     = pack2h(h0, h1);
            *(uint32_t*)(dsth + 4*u + 2) = pack2h(h2, h3);
            *(uint32_t*)(dstl + 4*u)     = pack2h(__float2half_rn(t.x - __half2float(h0)),
                                                  __float2half_rn(t.y - __half2float(h1)));
            *(uint32_t*)(dstl + 4*u + 2) = pack2h(__float2half_rn(t.z - __half2float(h2)),
                                                  __float2half_rn(t.w - __half2float(h3)));
        }
    }
    __syncthreads();

    // ---- out = xn + proj @ Wo + bo (3-term split MMA)
    int gq = lane >> 2, c2 = (lane & 3)*2;
    int row0 = qt*128 + 16*w + gq;
    const float* xb0 = g_xn + ((size_t)b*4096 + row0)*64;
    float* outb = out + ((size_t)b*4096 + row0)*64;

#pragma unroll
    for (int cj = 0; cj < 8; cj++) {
        float acc[4] = {0.f, 0.f, 0.f, 0.f};
        uint32_t waddr = smem_base + (uint32_t)(lane*KSTR + 8*cj)*2u;
        uint32_t wh0[4], wh1[4], wl0[4], wl1[4];
        LDSM4T(wh0, waddr);
        LDSM4T(wh1, waddr + (uint32_t)(32*KSTR*2));
        LDSM4T(wl0, waddr + (uint32_t)(MATS*2));
        LDSM4T(wl1, waddr + (uint32_t)(MATS*2) + (uint32_t)(32*KSTR*2));
        MMA_F16(acc, ph[0], wh0[0], wh0[1]);
        MMA_F16(acc, ph[1], wh0[2], wh0[3]);
        MMA_F16(acc, ph[2], wh1[0], wh1[1]);
        MMA_F16(acc, ph[3], wh1[2], wh1[3]);
        MMA_F16(acc, ph[0], wl0[0], wl0[1]);
        MMA_F16(acc, ph[1], wl0[2], wl0[3]);
        MMA_F16(acc, ph[2], wl1[0], wl1[1]);
        MMA_F16(acc, ph[3], wl1[2], wl1[3]);
        MMA_F16(acc, pl[0], wh0[0], wh0[1]);
        MMA_F16(acc, pl[1], wh0[2], wh0[3]);
        MMA_F16(acc, pl[2], wh1[0], wh1[1]);
        MMA_F16(acc, pl[3], wh1[2], wh1[3]);

        float2 bo2 = *(const float2*)(bo + 8*cj + c2);
        float2 x0  = *(const float2*)(xb0 + 8*cj + c2);
        float2 x1  = *(const float2*)(xb0 + 8*64 + 8*cj + c2);
        float2 r0; r0.x = acc[0] + bo2.x + x0.x; r0.y = acc[1] + bo2.y + x0.y;
        float2 r1; r1.x = acc[2] + bo2.x + x1.x; r1.y = acc[3] + bo2.y + x1.y;
        *(float2*)(outb + 8*cj + c2)        = r0;
        *(float2*)(outb + 8*64 + 8*cj + c2) = r1;
    }
}

// ---------------------------------------------------------------------------
extern "C" void kernel_launch(void* const* d_in, const int* in_sizes, int n_in,
                              void* d_out, int out_size)
{
    const float* x     = (const float*)d_in[0];
    const float* gamma = (const float*)d_in[1];
    const float* beta  = (const float*)d_in[2];
    const float* Wq    = (const float*)d_in[3];
    const float* bq    = (const float*)d_in[4];
    const float* Wk    = (const float*)d_in[5];
    const float* bk    = (const float*)d_in[6];
    const float* Wv    = (const float*)d_in[7];
    const float* bv    = (const float*)d_in[8];
    const float* Wo    = (const float*)d_in[9];
    const float* bo    = (const float*)d_in[10];
    float* out = (float*)d_out;

    cudaFuncSetAttribute(attn_kernel, cudaFuncAttributeMaxDynamicSharedMemorySize, ATTN_SMEM);

    gn_stats_kernel<<<256, 256>>>(x);
    qkv_kernel<<<256, 256>>>(x, gamma, beta, Wq, bq, Wk, bk, Wv, bv);
    attn_kernel<<<dim3(32, 4), 256, ATTN_SMEM>>>(Wo, bo, out);
}